// round 7
// baseline (speedup 1.0000x reference)
#include <cuda_runtime.h>
#include <cstdint>

#define M_B 128
#define N_F 1024
#define K_F 1024
#define KSPLIT 8
#define BN 64
#define KT 32
#define KCHUNK (K_F / KSPLIT)      /* 128 */
#define NITER (KCHUNK / KT)        /* 4 */
#define NBG 16                     /* nb groups */
#define GRID (NBG * KSPLIT)        /* 128 — single wave */

// Monotonic counters (replay-safe), 128B apart to avoid sector contention
__device__ unsigned int g_done[NBG * 32];
__device__ unsigned int g_init[NBG * 32];

// ---------------------------------------------------------------------------
__device__ __forceinline__ void cp_async16(void* smem, const void* gmem) {
    uint32_t s = (uint32_t)__cvta_generic_to_shared(smem);
    asm volatile("cp.async.cg.shared.global [%0], [%1], 16;\n" :: "r"(s), "l"(gmem));
}
__device__ __forceinline__ void cp_commit() {
    asm volatile("cp.async.commit_group;\n");
}
template <int N>
__device__ __forceinline__ void cp_wait() {
    asm volatile("cp.async.wait_group %0;\n" :: "n"(N));
}
__device__ __forceinline__ uint32_t f2tf32(float x) {
    uint32_t r;
    asm("cvt.rna.tf32.f32 %0, %1;" : "=r"(r) : "f"(x));
    return r;
}
__device__ __forceinline__ void red_add_v4(float* gptr, float a, float b,
                                           float c, float d) {
    asm volatile("red.global.add.v4.f32 [%0], {%1, %2, %3, %4};\n"
                 :: "l"(gptr), "f"(a), "f"(b), "f"(c), "f"(d) : "memory");
}

// ---------------------------------------------------------------------------
// Single kernel, 128 CTAs, NO global barrier:
//   CTA (nb, ks): split-K tf32 GEMM tile 128 x 64 over K-chunk ks.
//   CTA (nb, 0) additionally (overlapped with its stage-0 prefetch):
//     prep v,d for all 128 rows; out[:, nb cols] = bias + v.B + d.bctx;
//     fence; bump g_init[nb].
//   All CTAs finish by red.global.add.v4.f32 of their acc into out
//     (after a ~zero-cost replay-safe check that init already landed).
// ---------------------------------------------------------------------------
__global__ __launch_bounds__(256) void fused_kernel(
        const float* __restrict__ input,
        const float* __restrict__ codes,
        const float* __restrict__ weight,
        const float* __restrict__ A,
        const float* __restrict__ Bm,
        const float* __restrict__ bias,
        const float* __restrict__ bctx,
        float* __restrict__ out) {
    __shared__ float sA[2][128][KT + 4];   // 36864 B; aliased as s_out later
    __shared__ float sB[2][KT][BN + 8];    // stride 72, conflict-free
    __shared__ float s_vd[128][4];         // v0, v1, d0, d1 per row (leader)
    __shared__ unsigned int s_ticket;

    int tid = threadIdx.x;
    int bid = blockIdx.x;
    int nb_idx = bid & (NBG - 1);
    int ks = bid >> 4;
    int nb = nb_idx * BN;
    int k_base = ks * KCHUNK;
    bool leader = (ks == 0);

    int wid = tid >> 5, lane = tid & 31;
    int wm = wid & 3, wn = wid >> 2;
    int m_base = wm * 32, n_base = wn * 32;
    int g = lane >> 2, q = lane & 3;

    int a_row = tid >> 3, a_c4 = (tid & 7) * 4;
    int b_row = tid >> 4, b_c4 = (tid & 15) * 4;

    float acc[2][4][4];
    #pragma unroll
    for (int mi = 0; mi < 2; mi++)
        #pragma unroll
        for (int ni = 0; ni < 4; ni++)
            #pragma unroll
            for (int r = 0; r < 4; r++) acc[mi][ni][r] = 0.f;

    // ---- prefetch stage 0 (async; leader's init work overlaps it) ----
    {
        int k0 = k_base;
        #pragma unroll
        for (int t = 0; t < 4; t++) {
            int row = a_row + t * 32;
            cp_async16(&sA[0][row][a_c4], input + row * K_F + k0 + a_c4);
        }
        #pragma unroll
        for (int t = 0; t < 2; t++) {
            int row = b_row + t * 16;
            cp_async16(&sB[0][row][b_c4], weight + (k0 + row) * N_F + nb + b_c4);
        }
        cp_commit();
    }

    // ---- leader: prep v,d for all rows + init out columns ----
    if (leader) {
        int b = tid >> 1, h = tid & 1;
        const float4* in4 = reinterpret_cast<const float4*>(input) + b * 256 + h * 128;
        const float4* A4  = reinterpret_cast<const float4*>(A) + h * 256;
        float p0 = 0.f, p1 = 0.f;
        #pragma unroll 8
        for (int i = 0; i < 128; i++) {
            float4 x  = in4[i];
            float4 a0 = A4[i * 2];
            float4 a1 = A4[i * 2 + 1];
            p0 += x.x * a0.x + x.y * a0.z + x.z * a1.x + x.w * a1.z;
            p1 += x.x * a0.y + x.y * a0.w + x.z * a1.y + x.w * a1.w;
        }
        p0 += __shfl_xor_sync(0xFFFFFFFFu, p0, 1);
        p1 += __shfl_xor_sync(0xFFFFFFFFu, p1, 1);
        if (h == 0) {
            float c00 = codes[b * 4 + 0], c01 = codes[b * 4 + 1];
            float c10 = codes[b * 4 + 2], c11 = codes[b * 4 + 3];
            s_vd[b][0] = p0 * c00 + p1 * c10;
            s_vd[b][1] = p0 * c01 + p1 * c11;
            s_vd[b][2] = c00;
            s_vd[b][3] = c11;
        }
        __syncthreads();
        // init out[:, nb..nb+63] = bias + v.B + d.bctx
        int c4 = nb + (tid & 15) * 4;
        int r0 = tid >> 4;
        float4 bi = *reinterpret_cast<const float4*>(bias + c4);
        float4 B0 = *reinterpret_cast<const float4*>(Bm + c4);
        float4 B1 = *reinterpret_cast<const float4*>(Bm + N_F + c4);
        float4 e0 = *reinterpret_cast<const float4*>(bctx + c4);
        float4 e1 = *reinterpret_cast<const float4*>(bctx + N_F + c4);
        #pragma unroll
        for (int i = 0; i < 8; i++) {
            int row = r0 + i * 16;
            float v0 = s_vd[row][0], v1 = s_vd[row][1];
            float d0 = s_vd[row][2], d1 = s_vd[row][3];
            float4 o;
            o.x = bi.x + v0 * B0.x + v1 * B1.x + d0 * e0.x + d1 * e1.x;
            o.y = bi.y + v0 * B0.y + v1 * B1.y + d0 * e0.y + d1 * e1.y;
            o.z = bi.z + v0 * B0.z + v1 * B1.z + d0 * e0.z + d1 * e1.z;
            o.w = bi.w + v0 * B0.w + v1 * B1.w + d0 * e0.w + d1 * e1.w;
            *reinterpret_cast<float4*>(out + row * N_F + c4) = o;
        }
        __threadfence();
        __syncthreads();
        if (tid == 0) atomicAdd(&g_init[nb_idx * 32], 1u);
    }

    // ======================= GEMM mainloop =======================
    for (int s = 0; s < NITER; s++) {
        int buf = s & 1;
        if (s + 1 < NITER) {
            int k0 = k_base + (s + 1) * KT;
            int nbuf = (s + 1) & 1;
            #pragma unroll
            for (int t = 0; t < 4; t++) {
                int row = a_row + t * 32;
                cp_async16(&sA[nbuf][row][a_c4], input + row * K_F + k0 + a_c4);
            }
            #pragma unroll
            for (int t = 0; t < 2; t++) {
                int row = b_row + t * 16;
                cp_async16(&sB[nbuf][row][b_c4],
                           weight + (k0 + row) * N_F + nb + b_c4);
            }
            cp_commit();
            cp_wait<1>();
        } else {
            cp_wait<0>();
        }
        __syncthreads();

        #pragma unroll
        for (int kk = 0; kk < KT; kk += 8) {
            uint32_t afr[2][4], bfr[4][2];
            #pragma unroll
            for (int mi = 0; mi < 2; mi++) {
                int r0 = m_base + mi * 16 + g;
                afr[mi][0] = f2tf32(sA[buf][r0    ][kk + q    ]);
                afr[mi][1] = f2tf32(sA[buf][r0 + 8][kk + q    ]);
                afr[mi][2] = f2tf32(sA[buf][r0    ][kk + q + 4]);
                afr[mi][3] = f2tf32(sA[buf][r0 + 8][kk + q + 4]);
            }
            #pragma unroll
            for (int ni = 0; ni < 4; ni++) {
                int c0 = n_base + ni * 8 + g;
                bfr[ni][0] = f2tf32(sB[buf][kk + q    ][c0]);
                bfr[ni][1] = f2tf32(sB[buf][kk + q + 4][c0]);
            }
            #pragma unroll
            for (int mi = 0; mi < 2; mi++)
                #pragma unroll
                for (int ni = 0; ni < 4; ni++) {
                    asm volatile(
                        "mma.sync.aligned.m16n8k8.row.col.f32.tf32.tf32.f32 "
                        "{%0,%1,%2,%3}, {%4,%5,%6,%7}, {%8,%9}, {%0,%1,%2,%3};\n"
                        : "+f"(acc[mi][ni][0]), "+f"(acc[mi][ni][1]),
                          "+f"(acc[mi][ni][2]), "+f"(acc[mi][ni][3])
                        : "r"(afr[mi][0]), "r"(afr[mi][1]),
                          "r"(afr[mi][2]), "r"(afr[mi][3]),
                          "r"(bfr[ni][0]), "r"(bfr[ni][1]));
                }
        }
        __syncthreads();
    }

    // ---- transpose acc through smem (aliased over sA; safe post-sync) ----
    float* s_out = &sA[0][0][0];   // viewed as [128][72]; 36864 B fits exactly
    #pragma unroll
    for (int mi = 0; mi < 2; mi++)
        #pragma unroll
        for (int ni = 0; ni < 4; ni++) {
            int row = m_base + mi * 16 + g;
            int col = n_base + ni * 8 + q * 2;
            s_out[row * 72 + col]           = acc[mi][ni][0];
            s_out[row * 72 + col + 1]       = acc[mi][ni][1];
            s_out[(row + 8) * 72 + col]     = acc[mi][ni][2];
            s_out[(row + 8) * 72 + col + 1] = acc[mi][ni][3];
        }
    __syncthreads();

    // ---- replay-safe check that this group's init has landed ----
    if (tid == 0) {
        unsigned int ticket = atomicAdd(&g_done[nb_idx * 32], 1u);
        unsigned int target = (ticket >> 3) + 1u;   // 8 CTAs per group per replay
        volatile unsigned int* flag = &g_init[nb_idx * 32];
        while (*flag < target) { }
        __threadfence();
        s_ticket = target;  // dummy use
    }
    __syncthreads();

    // ---- accumulate into out via vector reduction ----
    {
        int c4 = (tid & 15) * 4;
        int r0 = tid >> 4;
        #pragma unroll
        for (int i = 0; i < 8; i++) {
            int row = r0 + i * 16;
            float* sp = &s_out[row * 72 + c4];
            red_add_v4(out + row * N_F + nb + c4, sp[0], sp[1], sp[2], sp[3]);
        }
    }
}

extern "C" void kernel_launch(void* const* d_in, const int* in_sizes, int n_in,
                              void* d_out, int out_size) {
    const float* input  = (const float*)d_in[0];
    const float* codes  = (const float*)d_in[1];
    const float* weight = (const float*)d_in[2];
    const float* A      = (const float*)d_in[3];
    const float* Bm     = (const float*)d_in[4];
    const float* bias   = (const float*)d_in[5];
    const float* bctx   = (const float*)d_in[6];
    float* out = (float*)d_out;

    fused_kernel<<<GRID, 256>>>(input, codes, weight, A, Bm, bias, bctx, out);
}

// round 8
// speedup vs baseline: 1.9915x; 1.9915x over previous
#include <cuda_runtime.h>
#include <cstdint>

#define M_B 128
#define N_F 1024
#define K_F 1024
#define KSPLIT 8
#define BN 64
#define KT 32
#define KCHUNK (K_F / KSPLIT)      /* 128 */
#define NITER (KCHUNK / KT)        /* 4 */
#define NBG 16                     /* nb groups */
#define GRID (NBG * KSPLIT)        /* 128 — single wave */

// Scratch (device globals)
__device__ float g_partial[KSPLIT * M_B * N_F];        // 4 MB split-K partials
__device__ float2 g_upart[NBG][KSPLIT][M_B];           // per-group u partials
__device__ unsigned int g_done[NBG * 32];              // monotonic tickets, 128B apart

// ---------------------------------------------------------------------------
__device__ __forceinline__ void cp_async16(void* smem, const void* gmem) {
    uint32_t s = (uint32_t)__cvta_generic_to_shared(smem);
    asm volatile("cp.async.cg.shared.global [%0], [%1], 16;\n" :: "r"(s), "l"(gmem));
}
__device__ __forceinline__ void cp_commit() {
    asm volatile("cp.async.commit_group;\n");
}
template <int N>
__device__ __forceinline__ void cp_wait() {
    asm volatile("cp.async.wait_group %0;\n" :: "n"(N));
}
__device__ __forceinline__ uint32_t f2tf32(float x) {
    uint32_t r;
    asm("cvt.rna.tf32.f32 %0, %1;" : "=r"(r) : "f"(x));
    return r;
}

// ---------------------------------------------------------------------------
// Single kernel, 128 CTAs, no global barrier, no spin, no output atomics:
//  CTA (nb, ks): split-K tf32 GEMM tile 128x64 for K-chunk ks
//                + redundant upart[nb][ks] (its own chunk of u = input.A)
//                fence; ticket = atomicAdd(g_done[nb]).
//  The CTA drawing the LAST ticket of its group reduces the 8 partials,
//  adds bias + v.B + d.bctx, writes out[:, nb..nb+63]. Others exit.
// ---------------------------------------------------------------------------
__global__ __launch_bounds__(256) void fused_kernel(
        const float* __restrict__ input,
        const float* __restrict__ codes,
        const float* __restrict__ weight,
        const float* __restrict__ A,
        const float* __restrict__ Bm,
        const float* __restrict__ bias,
        const float* __restrict__ bctx,
        float* __restrict__ out) {
    __shared__ float sA[2][128][KT + 4];   // stride 36: conflict-free frag loads
    __shared__ float sB[2][KT][BN + 8];    // stride 72: conflict-free frag loads
    __shared__ float s_vd[128][4];
    __shared__ unsigned int s_last;

    int tid = threadIdx.x;
    int bid = blockIdx.x;
    int nb_idx = bid & (NBG - 1);
    int ks = bid >> 4;
    int nb = nb_idx * BN;
    int k_base = ks * KCHUNK;

    int wid = tid >> 5, lane = tid & 31;
    int wm = wid & 3, wn = wid >> 2;
    int m_base = wm * 32, n_base = wn * 32;
    int g = lane >> 2, q = lane & 3;

    int a_row = tid >> 3, a_c4 = (tid & 7) * 4;
    int b_row = tid >> 4, b_c4 = (tid & 15) * 4;

    float acc[2][4][4];
    #pragma unroll
    for (int mi = 0; mi < 2; mi++)
        #pragma unroll
        for (int ni = 0; ni < 4; ni++)
            #pragma unroll
            for (int r = 0; r < 4; r++) acc[mi][ni][r] = 0.f;

    // ---- stage-0 prefetch (async) ----
    {
        int k0 = k_base;
        #pragma unroll
        for (int t = 0; t < 4; t++) {
            int row = a_row + t * 32;
            cp_async16(&sA[0][row][a_c4], input + row * K_F + k0 + a_c4);
        }
        #pragma unroll
        for (int t = 0; t < 2; t++) {
            int row = b_row + t * 16;
            cp_async16(&sB[0][row][b_c4], weight + (k0 + row) * N_F + nb + b_c4);
        }
        cp_commit();
    }

    // ---- upart for this (nb, ks): u-chunk = input[:, chunk] . A[chunk, :] ----
    {
        int b = tid >> 1, h = tid & 1;
        int k0 = k_base + h * 64;
        const float2* A2 = reinterpret_cast<const float2*>(A);
        float p0 = 0.f, p1 = 0.f;
        #pragma unroll
        for (int i = 0; i < 16; i++) {
            float4 x = *reinterpret_cast<const float4*>(input + b * K_F + k0 + i * 4);
            float2 a0 = A2[k0 + i * 4 + 0];
            float2 a1 = A2[k0 + i * 4 + 1];
            float2 a2 = A2[k0 + i * 4 + 2];
            float2 a3 = A2[k0 + i * 4 + 3];
            p0 += x.x * a0.x + x.y * a1.x + x.z * a2.x + x.w * a3.x;
            p1 += x.x * a0.y + x.y * a1.y + x.z * a2.y + x.w * a3.y;
        }
        p0 += __shfl_xor_sync(0xFFFFFFFFu, p0, 1);
        p1 += __shfl_xor_sync(0xFFFFFFFFu, p1, 1);
        if (h == 0) g_upart[nb_idx][ks][b] = make_float2(p0, p1);
    }

    // ======================= GEMM mainloop =======================
    for (int s = 0; s < NITER; s++) {
        int buf = s & 1;
        if (s + 1 < NITER) {
            int k0 = k_base + (s + 1) * KT;
            int nbuf = (s + 1) & 1;
            #pragma unroll
            for (int t = 0; t < 4; t++) {
                int row = a_row + t * 32;
                cp_async16(&sA[nbuf][row][a_c4], input + row * K_F + k0 + a_c4);
            }
            #pragma unroll
            for (int t = 0; t < 2; t++) {
                int row = b_row + t * 16;
                cp_async16(&sB[nbuf][row][b_c4],
                           weight + (k0 + row) * N_F + nb + b_c4);
            }
            cp_commit();
            cp_wait<1>();
        } else {
            cp_wait<0>();
        }
        __syncthreads();

        #pragma unroll
        for (int kk = 0; kk < KT; kk += 8) {
            uint32_t afr[2][4], bfr[4][2];
            #pragma unroll
            for (int mi = 0; mi < 2; mi++) {
                int r0 = m_base + mi * 16 + g;
                afr[mi][0] = f2tf32(sA[buf][r0    ][kk + q    ]);
                afr[mi][1] = f2tf32(sA[buf][r0 + 8][kk + q    ]);
                afr[mi][2] = f2tf32(sA[buf][r0    ][kk + q + 4]);
                afr[mi][3] = f2tf32(sA[buf][r0 + 8][kk + q + 4]);
            }
            #pragma unroll
            for (int ni = 0; ni < 4; ni++) {
                int c0 = n_base + ni * 8 + g;
                bfr[ni][0] = f2tf32(sB[buf][kk + q    ][c0]);
                bfr[ni][1] = f2tf32(sB[buf][kk + q + 4][c0]);
            }
            #pragma unroll
            for (int mi = 0; mi < 2; mi++)
                #pragma unroll
                for (int ni = 0; ni < 4; ni++) {
                    asm volatile(
                        "mma.sync.aligned.m16n8k8.row.col.f32.tf32.tf32.f32 "
                        "{%0,%1,%2,%3}, {%4,%5,%6,%7}, {%8,%9}, {%0,%1,%2,%3};\n"
                        : "+f"(acc[mi][ni][0]), "+f"(acc[mi][ni][1]),
                          "+f"(acc[mi][ni][2]), "+f"(acc[mi][ni][3])
                        : "r"(afr[mi][0]), "r"(afr[mi][1]),
                          "r"(afr[mi][2]), "r"(afr[mi][3]),
                          "r"(bfr[ni][0]), "r"(bfr[ni][1]));
                }
        }
        __syncthreads();
    }

    // ---- write split-K partials ----
    {
        float* part = g_partial + ks * (M_B * N_F);
        #pragma unroll
        for (int mi = 0; mi < 2; mi++)
            #pragma unroll
            for (int ni = 0; ni < 4; ni++) {
                int row = m_base + mi * 16 + g;
                int col = nb + n_base + ni * 8 + q * 2;
                part[row * N_F + col]           = acc[mi][ni][0];
                part[row * N_F + col + 1]       = acc[mi][ni][1];
                part[(row + 8) * N_F + col]     = acc[mi][ni][2];
                part[(row + 8) * N_F + col + 1] = acc[mi][ni][3];
            }
    }

    // ---- arrival: last CTA of group becomes the reducer (no spinning) ----
    __threadfence();
    __syncthreads();
    if (tid == 0) {
        unsigned int ticket = atomicAdd(&g_done[nb_idx * 32], 1u);
        s_last = ((ticket & (KSPLIT - 1)) == (KSPLIT - 1)) ? 1u : 0u;
    }
    __syncthreads();
    if (!s_last) return;
    __threadfence();   // acquire: producers' stores visible

    // ---- v, d for all rows from this group's uparts ----
    if (tid < M_B) {
        float u0 = 0.f, u1 = 0.f;
        #pragma unroll
        for (int k = 0; k < KSPLIT; k++) {
            float2 up = g_upart[nb_idx][k][tid];
            u0 += up.x; u1 += up.y;
        }
        float c00 = codes[tid * 4 + 0], c01 = codes[tid * 4 + 1];
        float c10 = codes[tid * 4 + 2], c11 = codes[tid * 4 + 3];
        s_vd[tid][0] = u0 * c00 + u1 * c10;
        s_vd[tid][1] = u0 * c01 + u1 * c11;
        s_vd[tid][2] = c00;
        s_vd[tid][3] = c11;
    }
    __syncthreads();

    // ---- reduce 8 partials + epilogue for cols [nb, nb+64) ----
    {
        int c4 = (tid & 15) * 4;
        int j4 = nb + c4;
        int r0 = tid >> 4;
        float4 bi = *reinterpret_cast<const float4*>(bias + j4);
        float4 B0 = *reinterpret_cast<const float4*>(Bm + j4);
        float4 B1 = *reinterpret_cast<const float4*>(Bm + N_F + j4);
        float4 e0 = *reinterpret_cast<const float4*>(bctx + j4);
        float4 e1 = *reinterpret_cast<const float4*>(bctx + N_F + j4);

        #pragma unroll
        for (int i = 0; i < 8; i++) {
            int row = r0 + i * 16;
            float4 s = *reinterpret_cast<const float4*>(&g_partial[row * N_F + j4]);
            #pragma unroll
            for (int k = 1; k < KSPLIT; k++) {
                float4 p = *reinterpret_cast<const float4*>(
                    &g_partial[k * (M_B * N_F) + row * N_F + j4]);
                s.x += p.x; s.y += p.y; s.z += p.z; s.w += p.w;
            }
            float v0 = s_vd[row][0], v1 = s_vd[row][1];
            float d0 = s_vd[row][2], d1 = s_vd[row][3];
            float4 o;
            o.x = s.x + bi.x + v0 * B0.x + v1 * B1.x + d0 * e0.x + d1 * e1.x;
            o.y = s.y + bi.y + v0 * B0.y + v1 * B1.y + d0 * e0.y + d1 * e1.y;
            o.z = s.z + bi.z + v0 * B0.z + v1 * B1.z + d0 * e0.z + d1 * e1.z;
            o.w = s.w + bi.w + v0 * B0.w + v1 * B1.w + d0 * e0.w + d1 * e1.w;
            *reinterpret_cast<float4*>(out + row * N_F + j4) = o;
        }
    }
}

extern "C" void kernel_launch(void* const* d_in, const int* in_sizes, int n_in,
                              void* d_out, int out_size) {
    const float* input  = (const float*)d_in[0];
    const float* codes  = (const float*)d_in[1];
    const float* weight = (const float*)d_in[2];
    const float* A      = (const float*)d_in[3];
    const float* Bm     = (const float*)d_in[4];
    const float* bias   = (const float*)d_in[5];
    const float* bctx   = (const float*)d_in[6];
    float* out = (float*)d_out;

    fused_kernel<<<GRID, 256>>>(input, codes, weight, A, Bm, bias, bctx, out);
}

// round 9
// speedup vs baseline: 2.9747x; 1.4937x over previous
#include <cuda_runtime.h>
#include <cstdint>

#define M_B 128
#define N_F 1024
#define K_F 1024
#define KSPLIT 8
#define BN 64
#define KCHUNK (K_F / KSPLIT)      /* 128 */
#define GRID 128                   /* 16 nb-groups x 8 ks — single wave, barrier-safe */

#define SA_STRIDE 132              /* 132 mod 32 = 4: (4g+q) distinct — conflict-free */
#define SB_STRIDE 72               /* 72 mod 32 = 8: (8q+g) distinct — conflict-free */
#define SMEM_BYTES ((128 * SA_STRIDE + KCHUNK * SB_STRIDE) * 4)   /* 104448 */

// Scratch (device globals: no allocation allowed in kernel_launch)
__device__ float g_partial[KSPLIT * M_B * N_F];   // 4 MB split-K partials
__device__ unsigned int g_cnt = 0;                 // monotonic ticket barrier

// ---------------------------------------------------------------------------
__device__ __forceinline__ void cp_async16(void* smem, const void* gmem) {
    uint32_t s = (uint32_t)__cvta_generic_to_shared(smem);
    asm volatile("cp.async.cg.shared.global [%0], [%1], 16;\n" :: "r"(s), "l"(gmem));
}
__device__ __forceinline__ void cp_commit() {
    asm volatile("cp.async.commit_group;\n");
}
template <int N>
__device__ __forceinline__ void cp_wait() {
    asm volatile("cp.async.wait_group %0;\n" :: "n"(N));
}
__device__ __forceinline__ uint32_t f2tf32(float x) {
    uint32_t r;
    asm("cvt.rna.tf32.f32 %0, %1;" : "=r"(r) : "f"(x));
    return r;
}

// ---------------------------------------------------------------------------
// Persistent kernel, 128 CTAs (single wave), monolithic K-stage:
//   All loads for the whole 128-K chunk issued at once (24 cp.async/thread),
//   ONE wait + ONE sync, then 16 unrolled kk MMA steps with no barriers.
//   Epilogue identical to the proven R6 shape: partials -> ticket barrier ->
//   per-row reduce + bias + rank-2 epilogue (prep hoisted pre-barrier).
// ---------------------------------------------------------------------------
__global__ __launch_bounds__(256, 1) void fused_kernel(
        const float* __restrict__ input,
        const float* __restrict__ codes,
        const float* __restrict__ weight,
        const float* __restrict__ A,
        const float* __restrict__ Bm,
        const float* __restrict__ bias,
        const float* __restrict__ bctx,
        float* __restrict__ out) {
    extern __shared__ float smem[];
    float (*sA)[SA_STRIDE] = reinterpret_cast<float(*)[SA_STRIDE]>(smem);
    float (*sB)[SB_STRIDE] = reinterpret_cast<float(*)[SB_STRIDE]>(smem + 128 * SA_STRIDE);
    __shared__ float s_red[8][2];

    int tid = threadIdx.x;
    int bid = blockIdx.x;

    int nb = (bid & 15) * BN;          // 16 nb-groups
    int ks = bid >> 4;                 // 8 ks
    int k_base = ks * KCHUNK;

    int wid = tid >> 5, lane = tid & 31;
    int wm = wid & 3, wn = wid >> 2;
    int m_base = wm * 32, n_base = wn * 32;
    int g = lane >> 2, q = lane & 3;

    // ---- issue ALL loads for the whole K-chunk (max MLP) ----
    {
        // sA: 128 rows x 128 cols = 4096 float4; 16 per thread
        int a_row = tid >> 5, a_c4 = (tid & 31) * 4;   // 8 rows per 256-thread pass
        #pragma unroll
        for (int t = 0; t < 16; t++) {
            int row = a_row + t * 8;
            cp_async16(&sA[row][a_c4], input + row * K_F + k_base + a_c4);
        }
        // sB: 128 rows x 64 cols = 2048 float4; 8 per thread
        int b_row = tid >> 4, b_c4 = (tid & 15) * 4;   // 16 rows per pass
        #pragma unroll
        for (int t = 0; t < 8; t++) {
            int row = b_row + t * 16;
            cp_async16(&sB[row][b_c4], weight + (k_base + row) * N_F + nb + b_c4);
        }
        cp_commit();
    }

    float acc[2][4][4];
    #pragma unroll
    for (int mi = 0; mi < 2; mi++)
        #pragma unroll
        for (int ni = 0; ni < 4; ni++)
            #pragma unroll
            for (int r = 0; r < 4; r++) acc[mi][ni][r] = 0.f;

    cp_wait<0>();
    __syncthreads();

    // ---- 16 unrolled kk steps, no barriers, ptxas free to hoist LDS ----
    #pragma unroll
    for (int kk = 0; kk < KCHUNK; kk += 8) {
        uint32_t afr[2][4], bfr[4][2];
        #pragma unroll
        for (int mi = 0; mi < 2; mi++) {
            int r0 = m_base + mi * 16 + g;
            afr[mi][0] = f2tf32(sA[r0    ][kk + q    ]);
            afr[mi][1] = f2tf32(sA[r0 + 8][kk + q    ]);
            afr[mi][2] = f2tf32(sA[r0    ][kk + q + 4]);
            afr[mi][3] = f2tf32(sA[r0 + 8][kk + q + 4]);
        }
        #pragma unroll
        for (int ni = 0; ni < 4; ni++) {
            int c0 = n_base + ni * 8 + g;
            bfr[ni][0] = f2tf32(sB[kk + q    ][c0]);
            bfr[ni][1] = f2tf32(sB[kk + q + 4][c0]);
        }
        #pragma unroll
        for (int mi = 0; mi < 2; mi++)
            #pragma unroll
            for (int ni = 0; ni < 4; ni++) {
                asm volatile(
                    "mma.sync.aligned.m16n8k8.row.col.f32.tf32.tf32.f32 "
                    "{%0,%1,%2,%3}, {%4,%5,%6,%7}, {%8,%9}, {%0,%1,%2,%3};\n"
                    : "+f"(acc[mi][ni][0]), "+f"(acc[mi][ni][1]),
                      "+f"(acc[mi][ni][2]), "+f"(acc[mi][ni][3])
                    : "r"(afr[mi][0]), "r"(afr[mi][1]),
                      "r"(afr[mi][2]), "r"(afr[mi][3]),
                      "r"(bfr[ni][0]), "r"(bfr[ni][1]));
            }
    }

    // ---- write split-K partials ----
    {
        float* part = g_partial + ks * (M_B * N_F);
        #pragma unroll
        for (int mi = 0; mi < 2; mi++)
            #pragma unroll
            for (int ni = 0; ni < 4; ni++) {
                int row = m_base + mi * 16 + g;
                int col = nb + n_base + ni * 8 + q * 2;
                part[row * N_F + col]           = acc[mi][ni][0];
                part[row * N_F + col + 1]       = acc[mi][ni][1];
                part[(row + 8) * N_F + col]     = acc[mi][ni][2];
                part[(row + 8) * N_F + col + 1] = acc[mi][ni][3];
            }
    }

    // ---- prep (pre-barrier, independent of partials): CTA b = bid ----
    float v0, v1, d0, d1;
    {
        int b = bid;
        float4 x = *reinterpret_cast<const float4*>(input + b * K_F + tid * 4);
        const float2* A2 = reinterpret_cast<const float2*>(A);
        float2 a0 = A2[tid * 4 + 0];
        float2 a1 = A2[tid * 4 + 1];
        float2 a2 = A2[tid * 4 + 2];
        float2 a3 = A2[tid * 4 + 3];
        float p0 = x.x * a0.x + x.y * a1.x + x.z * a2.x + x.w * a3.x;
        float p1 = x.x * a0.y + x.y * a1.y + x.z * a2.y + x.w * a3.y;
        #pragma unroll
        for (int off = 16; off > 0; off >>= 1) {
            p0 += __shfl_xor_sync(0xFFFFFFFFu, p0, off);
            p1 += __shfl_xor_sync(0xFFFFFFFFu, p1, off);
        }
        int w = tid >> 5;
        if (lane == 0) { s_red[w][0] = p0; s_red[w][1] = p1; }
        __syncthreads();
        float u0 = 0.f, u1 = 0.f;
        #pragma unroll
        for (int i = 0; i < 8; i++) { u0 += s_red[i][0]; u1 += s_red[i][1]; }
        float c00 = codes[b * 4 + 0], c01 = codes[b * 4 + 1];
        float c10 = codes[b * 4 + 2], c11 = codes[b * 4 + 3];
        v0 = u0 * c00 + u1 * c10;
        v1 = u0 * c01 + u1 * c11;
        d0 = c00;
        d1 = c11;
    }

    // ================== grid-wide ticket barrier ==================
    __threadfence();
    __syncthreads();
    if (tid == 0) {
        unsigned int ticket = atomicAdd(&g_cnt, 1u);
        unsigned int target = (ticket / GRID + 1u) * GRID;
        while (*((volatile unsigned int*)&g_cnt) < target) { }
    }
    __syncthreads();
    __threadfence();

    // ============ Phase 2: split-K reduce + epilogue (CTA b = bid) ============
    {
        int b = bid;
        int j4 = tid * 4;
        float4 s = *reinterpret_cast<const float4*>(&g_partial[b * N_F + j4]);
        #pragma unroll
        for (int k = 1; k < KSPLIT; k++) {
            float4 p = *reinterpret_cast<const float4*>(
                &g_partial[k * (M_B * N_F) + b * N_F + j4]);
            s.x += p.x; s.y += p.y; s.z += p.z; s.w += p.w;
        }
        float4 bi = *reinterpret_cast<const float4*>(bias + j4);
        float4 B0 = *reinterpret_cast<const float4*>(Bm + j4);
        float4 B1 = *reinterpret_cast<const float4*>(Bm + N_F + j4);
        float4 e0 = *reinterpret_cast<const float4*>(bctx + j4);
        float4 e1 = *reinterpret_cast<const float4*>(bctx + N_F + j4);

        float4 o;
        o.x = s.x + bi.x + v0 * B0.x + v1 * B1.x + d0 * e0.x + d1 * e1.x;
        o.y = s.y + bi.y + v0 * B0.y + v1 * B1.y + d0 * e0.y + d1 * e1.y;
        o.z = s.z + bi.z + v0 * B0.z + v1 * B1.z + d0 * e0.z + d1 * e1.z;
        o.w = s.w + bi.w + v0 * B0.w + v1 * B1.w + d0 * e0.w + d1 * e1.w;
        *reinterpret_cast<float4*>(out + b * N_F + j4) = o;
    }
}

extern "C" void kernel_launch(void* const* d_in, const int* in_sizes, int n_in,
                              void* d_out, int out_size) {
    const float* input  = (const float*)d_in[0];
    const float* codes  = (const float*)d_in[1];
    const float* weight = (const float*)d_in[2];
    const float* A      = (const float*)d_in[3];
    const float* Bm     = (const float*)d_in[4];
    const float* bias   = (const float*)d_in[5];
    const float* bctx   = (const float*)d_in[6];
    float* out = (float*)d_out;

    // Idempotent, deterministic, no allocation — safe under graph capture.
    cudaFuncSetAttribute(fused_kernel,
                         cudaFuncAttributeMaxDynamicSharedMemorySize, SMEM_BYTES);

    fused_kernel<<<GRID, 256, SMEM_BYTES>>>(input, codes, weight, A, Bm,
                                            bias, bctx, out);
}